// round 14
// baseline (speedup 1.0000x reference)
#include <cuda_runtime.h>
#include <cuda_bf16.h>

#define BB 64
#define SS 512
#define HH 1024
#define TT 17

#define VIT_BLOCKS  64
#define GEMM_BLOCKS 1024          // 16 blocks x 32 rows per batch

typedef unsigned long long u64;

__device__ __forceinline__ u64 fma2(u64 a, u64 b, u64 c) {
    u64 d;
    asm("fma.rn.f32x2 %0, %1, %2, %3;" : "=l"(d) : "l"(a), "l"(b), "l"(c));
    return d;
}
__device__ __forceinline__ u64 add2(u64 a, u64 b) {
    u64 d;
    asm("add.rn.f32x2 %0, %1, %2;" : "=l"(d) : "l"(a), "l"(b));
    return d;
}
__device__ __forceinline__ u64 pack2(float lo, float hi) {
    u64 d;
    asm("mov.b64 %0, {%1, %2};" : "=l"(d) : "f"(lo), "f"(hi));
    return d;
}

// per-batch GEMM completion counters (reset by zero_done before each run)
__device__ int g_done[BB];

__global__ void zero_done() {
    if (threadIdx.x < BB) g_done[threadIdx.x] = 0;
}

// ---------------- shared-memory union layout (43.7 KB static) -------------
// GEMM role:  xs0 [32*68 f] @0      (8704 B)
//             xs1            @8704   (8704 B)
//             wt0 [17*68 f]  @17408  (4624 B)
//             wt1            @22032  (4624 B)
//             ranks (int*64) @26656  (256 B)   [pre-phase only]
// VIT role:   fs  [512*17 f] @0      (34816 B)
//             bp  [512*17 u8]@34816  (8704 B)
//             sc  [2][20 f]  @43520  (160 B)
//             ranks          @26656  [pre-phase only; dead before fs fill]
#define SM_BYTES  43712
#define OFF_XS0   0
#define OFF_XS1   8704
#define OFF_WT0   17408
#define OFF_WT1   22032
#define OFF_RANK  26656
#define OFF_FS    0
#define OFF_BP    34816
#define OFF_SC    43520

#define GEMM_THREADS 128
#define ROWS_PB      32
#define KTILE        64
#define NKT          (HH / KTILE)
#define XS_STRIDE    68
#define WT_STRIDE    68

template<int T0, int CNT>
__device__ __forceinline__ void acc_tile(const float* __restrict__ xs_row,
                                         const float* __restrict__ wt, u64* acc)
{
#pragma unroll
    for (int c = 0; c < 16; c++) {
        ulonglong2 xv = *(const ulonglong2*)(xs_row + c * 4);
#pragma unroll
        for (int u = 0; u < CNT; u++) {
            ulonglong2 wv = *(const ulonglong2*)(wt + (T0 + u) * WT_STRIDE + c * 4);
            acc[u] = fma2(xv.x, wv.x, acc[u]);
            acc[u] = fma2(xv.y, wv.y, acc[u]);
        }
    }
}

// ---------------------------------------------------------------------------
// Fused kernel.
//   blocks [0, 64):        viterbi consumer, rank = blockIdx.x (nw-descending)
//   blocks [64, 1088):     GEMM producer, 16 blocks per ranked batch
// Every block locally computes the same rank permutation of nwords
// (descending, ties by index) so producers emit the longest sequences first
// and consumer b starts as early as possible.
// ---------------------------------------------------------------------------
__global__ __launch_bounds__(128) void fused_kernel(
    const float* __restrict__ x, const float* __restrict__ W,
    const float* __restrict__ bias, const float* __restrict__ trans,
    const float* __restrict__ start_trans, const float* __restrict__ end_trans,
    const int* __restrict__ nwords, float* __restrict__ out_tags,
    float* __restrict__ feats)
{
    __shared__ __align__(16) char smx[SM_BYTES];
    int* ranks = (int*)(smx + OFF_RANK);

    const int tid = threadIdx.x;

    // ---- rank permutation (all blocks, identical result) ----
    if (tid < BB) {
        const int nwi = nwords[tid];
        int rk = 0;
        for (int j = 0; j < BB; j++) {
            const int nwj = nwords[j];
            rk += (nwj > nwi) || (nwj == nwi && j < tid);
        }
        ranks[tid] = rk;
    }
    __syncthreads();

    if (blockIdx.x >= VIT_BLOCKS) {
        // =================== GEMM producer role ===================
        const int gb     = blockIdx.x - VIT_BLOCKS;
        const int myrank = gb >> 4;                 // 16 blocks per batch
        int batch = 0;
        for (int i = 0; i < BB; i++) if (ranks[i] == myrank) batch = i;
        __syncthreads();                            // ranks region now dead

        const int r    = tid & 31;
        const int g    = tid >> 5;                  // warp = tag group
        const int row0 = batch * SS + (gb & 15) * ROWS_PB;

        float* xs0 = (float*)(smx + OFF_XS0);
        float* xs1 = (float*)(smx + OFF_XS1);
        float* wt0 = (float*)(smx + OFF_WT0);
        float* wt1 = (float*)(smx + OFF_WT1);
        float* xsb[2] = { xs0, xs1 };
        float* wtb[2] = { wt0, wt1 };

        float4 px[4];
        float4 pw[3];

#pragma unroll
        for (int p = 0; p < 4; p++) {
            int idx = tid + p * GEMM_THREADS;
            int rr = idx >> 4, cc = idx & 15;
            px[p] = *(const float4*)(x + (size_t)(row0 + rr) * HH + cc * 4);
        }
#pragma unroll
        for (int p = 0; p < 3; p++) {
            int idx = tid + p * GEMM_THREADS;
            if (idx < TT * 16) {
                int t = idx >> 4, cc = idx & 15;
                pw[p] = *(const float4*)(W + (size_t)t * HH + cc * 4);
            }
        }

        u64 acc[5];
#pragma unroll
        for (int u = 0; u < 5; u++) acc[u] = 0ull;

#pragma unroll
        for (int p = 0; p < 4; p++) {
            int idx = tid + p * GEMM_THREADS;
            int rr = idx >> 4, cc = idx & 15;
            *(float4*)&xs0[rr * XS_STRIDE + cc * 4] = px[p];
        }
#pragma unroll
        for (int p = 0; p < 3; p++) {
            int idx = tid + p * GEMM_THREADS;
            if (idx < TT * 16) {
                int t = idx >> 4, cc = idx & 15;
                *(float4*)&wt0[t * WT_STRIDE + cc * 4] = pw[p];
            }
        }
        __syncthreads();

        for (int kt = 0; kt < NKT; kt++) {
            const int cur = kt & 1;

            if (kt + 1 < NKT) {
                const float* xk = x + (kt + 1) * KTILE;
#pragma unroll
                for (int p = 0; p < 4; p++) {
                    int idx = tid + p * GEMM_THREADS;
                    int rr = idx >> 4, cc = idx & 15;
                    px[p] = *(const float4*)(xk + (size_t)(row0 + rr) * HH + cc * 4);
                }
                const float* wk = W + (kt + 1) * KTILE;
#pragma unroll
                for (int p = 0; p < 3; p++) {
                    int idx = tid + p * GEMM_THREADS;
                    if (idx < TT * 16) {
                        int t = idx >> 4, cc = idx & 15;
                        pw[p] = *(const float4*)(wk + (size_t)t * HH + cc * 4);
                    }
                }
            }

            const float* xs_row = &xsb[cur][r * XS_STRIDE];
            if      (g == 0) acc_tile<0,  5>(xs_row, wtb[cur], acc);
            else if (g == 1) acc_tile<5,  4>(xs_row, wtb[cur], acc);
            else if (g == 2) acc_tile<9,  4>(xs_row, wtb[cur], acc);
            else             acc_tile<13, 4>(xs_row, wtb[cur], acc);

            if (kt + 1 < NKT) {
                const int nxt = cur ^ 1;
#pragma unroll
                for (int p = 0; p < 4; p++) {
                    int idx = tid + p * GEMM_THREADS;
                    int rr = idx >> 4, cc = idx & 15;
                    *(float4*)&xsb[nxt][rr * XS_STRIDE + cc * 4] = px[p];
                }
#pragma unroll
                for (int p = 0; p < 3; p++) {
                    int idx = tid + p * GEMM_THREADS;
                    if (idx < TT * 16) {
                        int t = idx >> 4, cc = idx & 15;
                        *(float4*)&wtb[nxt][t * WT_STRIDE + cc * 4] = pw[p];
                    }
                }
                __syncthreads();
            }
        }

        const int t0  = (g == 0) ? 0 : (g == 1) ? 5 : (g == 2) ? 9 : 13;
        const int cnt = (g == 0) ? 5 : 4;
        float* o = feats + (size_t)(row0 + r) * TT;
#pragma unroll
        for (int u = 0; u < 5; u++) {
            if (u < cnt) {
                float2 p = *(float2*)&acc[u];
                o[t0 + u] = p.x + p.y + bias[t0 + u];
            }
        }

        // publish: all stores visible, then bump the batch counter
        __threadfence();
        __syncthreads();
        if (tid == 0) atomicAdd(&g_done[batch], 1);
        return;
    }

    // =================== Viterbi consumer role ===================
    const int myrank = blockIdx.x;
    int batch = 0;
    for (int i = 0; i < BB; i++) if (ranks[i] == myrank) batch = i;
    __syncthreads();                                // ranks region now dead

    const int nw = nwords[batch];

    // wait until all 16 producer blocks for this batch are done
    if (tid == 0) {
        int v;
        do {
            asm volatile("ld.acquire.gpu.global.b32 %0, [%1];"
                         : "=r"(v) : "l"(&g_done[batch]) : "memory");
            if (v < 16) __nanosleep(200);
        } while (v < 16);
    }
    __syncthreads();

    float* fs = (float*)(smx + OFF_FS);
    unsigned char* bp = (unsigned char*)(smx + OFF_BP);
    float* scp = (float*)(smx + OFF_SC);            // sc[k][j] = scp[k*20+j]

    // cooperative feats fill (only rows < nw are read)
    const float4* fb4 = (const float4*)(feats + (size_t)batch * SS * TT);
    const int n4 = (nw * TT + 3) >> 2;
    for (int i = tid; i < n4; i += 128)
        ((float4*)fs)[i] = fb4[i];
    __syncthreads();

    if (tid >= 32) return;                          // warps 1-3 done

    const int jj = (tid < TT) ? tid : (TT - 1);

    float tcol[TT];
#pragma unroll
    for (int i = 0; i < TT; i++) tcol[i] = trans[i * TT + jj];
    u64 tc2[8];
#pragma unroll
    for (int p = 0; p < 8; p++) tc2[p] = pack2(tcol[2 * p], tcol[2 * p + 1]);
    const float tc16 = tcol[16];

    float score = start_trans[jj] + fs[jj];         // t = 0 (always unmasked)
    if (tid < TT) scp[1 * 20 + jj] = score;
    __syncwarp();

    for (int t = 1; t < nw; t++) {
        const float* s = scp + (t & 1) * 20;
        const float f  = fs[t * TT + jj];

        ulonglong2 sA = *(const ulonglong2*)(s);
        ulonglong2 sB = *(const ulonglong2*)(s + 4);
        ulonglong2 sC = *(const ulonglong2*)(s + 8);
        ulonglong2 sD = *(const ulonglong2*)(s + 12);
        float s16 = s[16];

        u64 c2[8];
        c2[0] = add2(sA.x, tc2[0]); c2[1] = add2(sA.y, tc2[1]);
        c2[2] = add2(sB.x, tc2[2]); c2[3] = add2(sB.y, tc2[3]);
        c2[4] = add2(sC.x, tc2[4]); c2[5] = add2(sC.y, tc2[5]);
        c2[6] = add2(sD.x, tc2[6]); c2[7] = add2(sD.y, tc2[7]);
        float c16 = s16 + tc16;

        float c[16];
#pragma unroll
        for (int p = 0; p < 8; p++) {
            float2 cp = *(float2*)&c2[p];
            c[2 * p] = cp.x; c[2 * p + 1] = cp.y;
        }

        float m8[8];
#pragma unroll
        for (int p = 0; p < 8; p++) m8[p] = fmaxf(c[2 * p], c[2 * p + 1]);
        float m4[4];
#pragma unroll
        for (int p = 0; p < 4; p++) m4[p] = fmaxf(m8[2 * p], m8[2 * p + 1]);
        float bv = fmaxf(fmaxf(fmaxf(m4[0], m4[1]), fmaxf(m4[2], m4[3])), c16);

        score = bv + f;
        if (tid < TT) scp[((t + 1) & 1) * 20 + jj] = score;
        __syncwarp();

        // first index equal to bv (off the serial chain)
        int e[16];
#pragma unroll
        for (int i = 0; i < 16; i++) e[i] = (c[i] == bv) ? i : 31;
        int e16 = (c16 == bv) ? 16 : 31;
        int i8[8];
#pragma unroll
        for (int p = 0; p < 8; p++) i8[p] = min(e[2 * p], e[2 * p + 1]);
        int i4[4];
#pragma unroll
        for (int p = 0; p < 4; p++) i4[p] = min(i8[2 * p], i8[2 * p + 1]);
        int bi = min(min(min(i4[0], i4[1]), min(i4[2], i4[3])), e16);

        if (tid < TT) bp[t * TT + jj] = (unsigned char)bi;
    }

    __syncwarp();

    float* o = out_tags + (size_t)batch * SS;
    for (int t = nw + tid; t < SS; t += 32) o[t] = 0.0f;   // masked tail

    if (tid == 0) {
        const float* s = scp + (nw & 1) * 20;
        int cur = 0;
        float bv = s[0] + end_trans[0];
#pragma unroll
        for (int i = 1; i < TT; i++) {
            float v = s[i] + end_trans[i];
            if (v > bv) { bv = v; cur = i; }
        }
        for (int t = nw - 1; t >= 1; t--) {
            o[t] = (float)cur;
            cur = bp[t * TT + cur];
        }
        o[0] = (float)cur;   // nwords >= 1
    }
}

// ---------------------------------------------------------------------------
// Inputs: x, W, b, transitions, start_trans, end_trans, nwords
// Output: [padded_tags (B*S) | feats (B*S*T)] float32
// ---------------------------------------------------------------------------
extern "C" void kernel_launch(void* const* d_in, const int* in_sizes, int n_in,
                              void* d_out, int out_size)
{
    const float* x     = (const float*)d_in[0];
    const float* W     = (const float*)d_in[1];
    const float* bias  = (const float*)d_in[2];
    const float* trans = (const float*)d_in[3];
    const float* st    = (const float*)d_in[4];
    const float* en    = (const float*)d_in[5];
    const int*   nw    = (const int*)d_in[6];

    float* out   = (float*)d_out;
    float* tags  = out;                // B*S
    float* feats = out + BB * SS;      // B*S*T

    zero_done<<<1, 64>>>();
    fused_kernel<<<VIT_BLOCKS + GEMM_BLOCKS, 128>>>(
        x, W, bias, trans, st, en, nw, tags, feats);
}